// round 1
// baseline (speedup 1.0000x reference)
#include <cuda_runtime.h>
#include <cstdint>

// Problem dims
#define Bn    32
#define Cn    256
#define HWn   1024
#define NROWS 32768      // B*H*W
#define Kn    1024
#define NTENS 8388608    // B*C*H*W

// Scratch (device globals — no allocation allowed)
__device__ float  g_se[Kn];
__device__ int    g_idx[NROWS];
__device__ double g_loss;

// ---------------------------------------------------------------------------
// Kernel 1: per-code squared norms (fp64 accumulate -> fp32), reset loss acc.
// 128 blocks x 256 threads, one warp per code.
// ---------------------------------------------------------------------------
__global__ void k_prep(const float* __restrict__ emb) {
    if (blockIdx.x == 0 && threadIdx.x == 0) g_loss = 0.0;
    int warp = (blockIdx.x * blockDim.x + threadIdx.x) >> 5;
    int lane = threadIdx.x & 31;
    if (warp < Kn) {
        const float* e = emb + warp * Cn;
        double s = 0.0;
        #pragma unroll
        for (int c = lane; c < Cn; c += 32) {
            double v = (double)e[c];
            s += v * v;
        }
        #pragma unroll
        for (int o = 16; o; o >>= 1) s += __shfl_xor_sync(0xffffffffu, s, o);
        if (lane == 0) g_se[warp] = (float)s;
    }
}

// ---------------------------------------------------------------------------
// Kernel 2: fused distance-GEMM + argmin.
// Block = 128 threads, TM=128 rows x (all 1024 codes in TN=64 chunks), C=256.
// Each thread: 8 rows x 8 codes register tile. Distances replicate the
// reference fp32 rounding: D = fl( fl(sx + se) - fl(2 * dot) ).
// Tie-break = lowest code index via packed u64 (f32 bits are positive).
// ---------------------------------------------------------------------------
#define TM    128
#define TN    64
#define PITCH 264   // floats per smem row (16B aligned, swizzled below)

__device__ __forceinline__ int swz(int r, int c) {
    // XOR-swizzle float4 groups so rows differing by 8 hit different banks.
    return r * PITCH + ((((c >> 2) ^ ((r >> 3) & 7)) << 2) | (c & 3));
}

__global__ __launch_bounds__(128, 1)
void k_argmin(const float* __restrict__ x, const float* __restrict__ emb) {
    extern __shared__ float sm[];
    float* xs  = sm;                    // TM * PITCH
    float* es  = xs + TM * PITCH;       // TN * PITCH
    float* sxs = es + TN * PITCH;       // TM
    float* ses = sxs + TM;              // TN

    const int tid  = threadIdx.x;
    const int row0 = blockIdx.x * TM;          // 256 tiles
    const int b    = row0 >> 10;               // 1024 rows per batch image
    const int hw0  = row0 & 1023;
    const float* xb = x + (size_t)b * (Cn * HWn) + hw0;

    // Load x tile transposed: xs[r][c] = x[b, c, hw0+r].
    // Pass p loads column c=p for row r=tid (coalesced over r). Each thread
    // sees its full row -> accumulate sx in fp64 inline.
    {
        double s = 0.0;
        for (int c = 0; c < Cn; c++) {
            float v = xb[c * HWn + tid];
            xs[swz(tid, c)] = v;
            s += (double)v * (double)v;
        }
        sxs[tid] = (float)s;
    }

    const int rg = tid >> 3;      // 0..15 row group
    const int cg = tid & 7;       // 0..7 code group
    const int r0 = rg * 8;

    unsigned long long best[8];
    #pragma unroll
    for (int i = 0; i < 8; i++) best[i] = ~0ull;

    for (int kt = 0; kt < Kn / TN; kt++) {
        const int k0 = kt * TN;
        __syncthreads();   // protect es reuse (and xs readiness on kt==0)
        for (int i = tid; i < TN * Cn; i += 128) {
            int kk = i >> 8;      // Cn == 256
            int c  = i & 255;
            es[swz(kk, c)] = emb[(k0 + kk) * Cn + c];
        }
        if (tid < TN) ses[tid] = g_se[k0 + tid];
        __syncthreads();

        float acc[8][8];
        #pragma unroll
        for (int i = 0; i < 8; i++)
            #pragma unroll
            for (int j = 0; j < 8; j++) acc[i][j] = 0.f;

        #pragma unroll 2
        for (int c = 0; c < Cn; c += 4) {
            float4 xv[8];
            #pragma unroll
            for (int i = 0; i < 8; i++)
                xv[i] = *(const float4*)&xs[swz(r0 + i, c)];
            #pragma unroll
            for (int j = 0; j < 8; j++) {
                float4 ev = *(const float4*)&es[swz(cg * 8 + j, c)];
                #pragma unroll
                for (int i = 0; i < 8; i++) {
                    acc[i][j] = fmaf(xv[i].x, ev.x, acc[i][j]);
                    acc[i][j] = fmaf(xv[i].y, ev.y, acc[i][j]);
                    acc[i][j] = fmaf(xv[i].z, ev.z, acc[i][j]);
                    acc[i][j] = fmaf(xv[i].w, ev.w, acc[i][j]);
                }
            }
        }

        // D = fl( fl(sx + se) - fl(2*t) )  — must NOT be FMA-contracted.
        #pragma unroll
        for (int i = 0; i < 8; i++) {
            float sx = sxs[r0 + i];
            #pragma unroll
            for (int j = 0; j < 8; j++) {
                int k = k0 + cg * 8 + j;
                float c1 = __fadd_rn(sx, ses[cg * 8 + j]);
                float c2 = __fmul_rn(2.0f, acc[i][j]);
                float D  = __fsub_rn(c1, c2);
                unsigned long long key =
                    ((unsigned long long)__float_as_uint(D) << 32) | (unsigned)k;
                if (key < best[i]) best[i] = key;
            }
        }
    }

    // Reduce best over the 8 code-group lanes sharing each row.
    #pragma unroll
    for (int i = 0; i < 8; i++) {
        unsigned long long k = best[i];
        #pragma unroll
        for (int o = 1; o < 8; o <<= 1) {
            unsigned long long other = __shfl_xor_sync(0xffffffffu, k, o);
            if (other < k) k = other;
        }
        if (cg == 0) g_idx[row0 + r0 + i] = (int)(k & 0xffffffffu);
    }
}

// ---------------------------------------------------------------------------
// Kernel 3: gather codes, write output in [B,C,H,W], accumulate MSE sum.
// Grid 512 = 32 b x 16 hw-segments(64 each). Thread: 4 hw (float4) x 16 c.
// ---------------------------------------------------------------------------
__global__ __launch_bounds__(256)
void k_output(const float* __restrict__ x, const float* __restrict__ emb,
              float* __restrict__ out, int write_tensor) {
    int blk   = blockIdx.x;
    int b     = blk >> 4;
    int hw0   = (blk & 15) * 64;
    int tid   = threadIdx.x;
    int h4    = tid & 15;          // float4 group within 64 hw
    int cgv   = tid >> 4;          // 0..15
    int hw    = hw0 + h4 * 4;
    int n0    = b * HWn + hw;
    int i0 = g_idx[n0], i1 = g_idx[n0 + 1], i2 = g_idx[n0 + 2], i3 = g_idx[n0 + 3];
    const float* xb = x   + (size_t)b * (Cn * HWn) + hw;
    float*       ob = out + (size_t)b * (Cn * HWn) + hw;

    float accl = 0.f;
    #pragma unroll 4
    for (int cc = 0; cc < 16; cc++) {
        int c = cgv * 16 + cc;
        float q0 = emb[i0 * Cn + c];
        float q1 = emb[i1 * Cn + c];
        float q2 = emb[i2 * Cn + c];
        float q3 = emb[i3 * Cn + c];
        float4 xv = *(const float4*)&xb[c * HWn];
        float d0 = q0 - xv.x, d1 = q1 - xv.y, d2 = q2 - xv.z, d3 = q3 - xv.w;
        accl += d0 * d0 + d1 * d1 + d2 * d2 + d3 * d3;
        if (write_tensor) {
            float4 qv = make_float4(q0, q1, q2, q3);
            *(float4*)&ob[c * HWn] = qv;
        }
    }

    __shared__ float red[256];
    red[tid] = accl;
    __syncthreads();
    for (int s = 128; s; s >>= 1) {
        if (tid < s) red[tid] += red[tid + s];
        __syncthreads();
    }
    if (tid == 0) atomicAdd(&g_loss, (double)red[0]);
}

// ---------------------------------------------------------------------------
// Kernel 4: finalize loss = 1.25 * mean((q - x)^2)
// ---------------------------------------------------------------------------
__global__ void k_finalize(float* out, int pos) {
    out[pos] = (float)(1.25 * g_loss / (double)NTENS);
}

extern "C" void kernel_launch(void* const* d_in, const int* in_sizes, int n_in,
                              void* d_out, int out_size) {
    const float* x   = (const float*)d_in[0];   // [B,C,H,W] fp32
    const float* emb = (const float*)d_in[1];   // [K,C] fp32
    float* out = (float*)d_out;

    size_t smem = (size_t)(TM * PITCH + TN * PITCH + TM + TN) * sizeof(float);
    cudaFuncSetAttribute(k_argmin, cudaFuncAttributeMaxDynamicSharedMemorySize,
                         (int)smem);

    k_prep<<<128, 256>>>(emb);
    k_argmin<<<NROWS / TM, 128, smem>>>(x, emb);

    int write_tensor = (out_size >= NTENS) ? 1 : 0;
    k_output<<<512, 256>>>(x, emb, out, write_tensor);

    if (out_size == NTENS + 1)      k_finalize<<<1, 1>>>(out, NTENS);
    else if (out_size == 1)         k_finalize<<<1, 1>>>(out, 0);
    // out_size == NTENS: tensor only, nothing else to write.
}

// round 4
// speedup vs baseline: 1.6395x; 1.6395x over previous
#include <cuda_runtime.h>
#include <cuda_fp16.h>
#include <cstdint>

#define Bn    32
#define Cn    256
#define HWn   1024
#define NROWS 32768
#define Kn    1024
#define NTENS 8388608

// ---------------- scratch (device globals; no allocation allowed) ----------
__device__ __align__(16) __half g_Ah2[NROWS * Cn];
__device__ __align__(16) __half g_Am2[NROWS * Cn];
__device__ __align__(16) __half g_Eh2[Kn * Cn];
__device__ __align__(16) __half g_Em2[Kn * Cn];
__device__ float  g_sx[NROWS];
__device__ float  g_se[Kn];
__device__ int    g_idx[NROWS];
__device__ int    g_fcount;
__device__ int    g_flist[NROWS];
__device__ double g_loss;

__device__ const __half* const g_As2[3] = {g_Ah2, g_Ah2, g_Am2};
__device__ const __half* const g_Bs2[3] = {g_Eh2, g_Em2, g_Eh2};

// ---------------- PTX helpers (baseline sm_80+ features only) --------------
__device__ __forceinline__ uint32_t cvta_s(const void* p) {
    return (uint32_t)__cvta_generic_to_shared(p);
}
__device__ __forceinline__ void cp16(uint32_t dst, const void* src) {
    asm volatile("cp.async.cg.shared.global [%0], [%1], 16;"
                 :: "r"(dst), "l"(src) : "memory");
}
__device__ __forceinline__ void cp_commit() {
    asm volatile("cp.async.commit_group;" ::: "memory");
}
template <int N> __device__ __forceinline__ void cp_wait() {
    asm volatile("cp.async.wait_group %0;" :: "n"(N) : "memory");
}
__device__ __forceinline__ void ldsm4(uint32_t* r, uint32_t a) {
    asm volatile("ldmatrix.sync.aligned.m8n8.x4.shared.b16 {%0,%1,%2,%3},[%4];"
                 : "=r"(r[0]), "=r"(r[1]), "=r"(r[2]), "=r"(r[3]) : "r"(a));
}
__device__ __forceinline__ void mma16816(float* c, const uint32_t* a, const uint32_t* b) {
    asm volatile(
        "mma.sync.aligned.m16n8k16.row.col.f32.f16.f16.f32 "
        "{%0,%1,%2,%3},{%4,%5,%6,%7},{%8,%9},{%0,%1,%2,%3};"
        : "+f"(c[0]), "+f"(c[1]), "+f"(c[2]), "+f"(c[3])
        : "r"(a[0]), "r"(a[1]), "r"(a[2]), "r"(a[3]), "r"(b[0]), "r"(b[1]));
}

// ---------------------------------------------------------------------------
// Prep 1: emb -> fp16 (h,m) splits + se (fp64->fp32); reset accumulators.
// ---------------------------------------------------------------------------
__global__ void k_prepe(const float* __restrict__ emb) {
    int k = blockIdx.x * 256 + threadIdx.x;
    if (k == 0) { g_loss = 0.0; g_fcount = 0; }
    if (k >= Kn) return;
    const float* e = emb + (size_t)k * Cn;
    double s = 0.0;
    for (int g = 0; g < 32; g++) {
        float4 v0 = *(const float4*)(e + g * 8);
        float4 v1 = *(const float4*)(e + g * 8 + 4);
        float vv[8] = {v0.x, v0.y, v0.z, v0.w, v1.x, v1.y, v1.z, v1.w};
        __align__(16) __half hb[8], mb[8];
        #pragma unroll
        for (int i = 0; i < 8; i++) {
            float v = vv[i];
            s += (double)v * (double)v;
            __half h = __float2half_rn(v);
            hb[i] = h;
            mb[i] = __float2half_rn(v - __half2float(h));
        }
        size_t o = (size_t)k * Cn + g * 8;
        *(uint4*)&g_Eh2[o] = *(uint4*)hb;
        *(uint4*)&g_Em2[o] = *(uint4*)mb;
    }
    g_se[k] = (float)s;
}

// ---------------------------------------------------------------------------
// Prep 2: transpose x [B,C,H,W] -> fp16 (h,m) splits [n][c] + sx per row.
// ---------------------------------------------------------------------------
__global__ __launch_bounds__(256) void k_split(const float* __restrict__ x) {
    __shared__ float  xs[256 * 33];
    __shared__ double ps[8][32];
    int blk = blockIdx.x;
    int b   = blk >> 5;
    int hw0 = (blk & 31) * 32;
    int tid = threadIdx.x;

    const float* xb = x + (size_t)b * (Cn * HWn) + hw0;
    #pragma unroll
    for (int t = 0; t < 8; t++) {
        int idx = tid + t * 256;
        int c = idx >> 3, g = idx & 7;
        float4 v = *(const float4*)(xb + (size_t)c * HWn + g * 4);
        xs[c * 33 + g * 4 + 0] = v.x;
        xs[c * 33 + g * 4 + 1] = v.y;
        xs[c * 33 + g * 4 + 2] = v.z;
        xs[c * 33 + g * 4 + 3] = v.w;
    }
    __syncthreads();

    int hw = tid & 31;
    int cs = tid >> 5;
    size_t n = (size_t)b * HWn + hw0 + hw;
    double s = 0.0;
    #pragma unroll 1
    for (int g = 0; g < 4; g++) {
        __align__(16) __half hb[8], mb[8];
        #pragma unroll
        for (int i = 0; i < 8; i++) {
            int c = cs * 32 + g * 8 + i;
            float v = xs[c * 33 + hw];
            s += (double)v * (double)v;
            __half h = __float2half_rn(v);
            hb[i] = h;
            mb[i] = __float2half_rn(v - __half2float(h));
        }
        size_t o = n * Cn + cs * 32 + g * 8;
        *(uint4*)&g_Ah2[o] = *(uint4*)hb;
        *(uint4*)&g_Am2[o] = *(uint4*)mb;
    }
    ps[cs][hw] = s;
    __syncthreads();
    if (tid < 32) {
        double t = 0.0;
        #pragma unroll
        for (int j = 0; j < 8; j++) t += ps[j][tid];
        g_sx[(size_t)b * HWn + hw0 + tid] = (float)t;
    }
}

// ---------------------------------------------------------------------------
// Phase 1: fp16 split GEMM (K=768) + per-row top-2 + margin-certified argmin.
// ---------------------------------------------------------------------------
#define STAGES   3
#define STG      32768                    // A 16KB + B 16KB per stage
#define SM_SES   (STAGES * STG)           // 98304
#define SM_SXS   (SM_SES + 4096)
#define SM_TOTAL (SM_SXS + 512)
#define GAPT     1e-4f

__global__ __launch_bounds__(256, 2) void k_mma() {
    extern __shared__ char sm[];
    const uint32_t smem = cvta_s(sm);
    float* ses = (float*)(sm + SM_SES);
    float* sxs = (float*)(sm + SM_SXS);

    const int tid  = threadIdx.x;
    const int lane = tid & 31;
    const int wid  = tid >> 5;
    const int wm   = wid & 3;
    const int wn   = wid >> 2;
    const int row0 = blockIdx.x * 128;

    for (int i = tid; i < Kn; i += 256) ses[i] = g_se[i];
    if (tid < 128) sxs[tid] = g_sx[row0 + tid];

    const int arow0 = wm * 32 + (lane & 15);
    const int akofs = (lane >> 4);
    const int bnofs = ((lane >> 4) << 3) + (lane & 7);
    const int bkofs = ((lane >> 3) & 1);

    unsigned long long b1[4] = {~0ull, ~0ull, ~0ull, ~0ull};
    unsigned long long b2[4] = {~0ull, ~0ull, ~0ull, ~0ull};

    for (int cb = 0; cb < 8; cb++) {
        const int n0 = cb * 128;
        float acc[2][8][4];
        #pragma unroll
        for (int i = 0; i < 2; i++)
            #pragma unroll
            for (int j = 0; j < 8; j++)
                #pragma unroll
                for (int c = 0; c < 4; c++) acc[i][j][c] = 0.f;

        #define ISSUE(S)  do {                                                   \
            int _s = (S);                                                        \
            int _ci = _s >> 2, _co = (_s & 3) * 64;                              \
            const __half* _ga = g_As2[_ci];                                      \
            const __half* _gb = g_Bs2[_ci];                                      \
            uint32_t _base = smem + (uint32_t)(_s % STAGES) * STG;               \
            _Pragma("unroll")                                                    \
            for (int _t = 0; _t < 4; _t++) {                                     \
                int _idx = tid + _t * 256;                                       \
                int _r = _idx >> 3, _kc = _idx & 7;                              \
                uint32_t _sw = (uint32_t)((_kc ^ (_r & 7)) << 4);                \
                cp16(_base + _r * 128 + _sw,                                     \
                     _ga + (size_t)(row0 + _r) * Cn + _co + _kc * 8);            \
                cp16(_base + 16384 + _r * 128 + _sw,                             \
                     _gb + (size_t)(n0 + _r) * Cn + _co + _kc * 8);              \
            }                                                                    \
            cp_commit();                                                         \
        } while (0)

        ISSUE(0);
        ISSUE(1);

        for (int s = 0; s < 12; s++) {
            if (s < 10) cp_wait<1>(); else cp_wait<0>();
            __syncthreads();
            if (s + 2 < 12) ISSUE(s + 2);

            const uint32_t sA = smem + (uint32_t)(s % STAGES) * STG;
            const uint32_t sB = sA + 16384;

            #pragma unroll
            for (int ks = 0; ks < 4; ks++) {
                uint32_t af[2][4], bf[4][4];
                #pragma unroll
                for (int i = 0; i < 2; i++) {
                    int r = arow0 + i * 16;
                    int kc = ks * 2 + akofs;
                    ldsm4(af[i], sA + r * 128 + ((kc ^ (r & 7)) << 4));
                }
                #pragma unroll
                for (int p = 0; p < 4; p++) {
                    int n = wn * 64 + p * 16 + bnofs;
                    int kc = ks * 2 + bkofs;
                    ldsm4(bf[p], sB + n * 128 + ((kc ^ (n & 7)) << 4));
                }
                #pragma unroll
                for (int i = 0; i < 2; i++)
                    #pragma unroll
                    for (int j = 0; j < 8; j++)
                        mma16816(acc[i][j], af[i], &bf[j >> 1][(j & 1) * 2]);
            }
        }
        #undef ISSUE

        // distances with exact reference rounding + top-2 update
        #pragma unroll
        for (int i = 0; i < 2; i++)
            #pragma unroll
            for (int j = 0; j < 8; j++)
                #pragma unroll
                for (int c = 0; c < 4; c++) {
                    int n    = n0 + wn * 64 + j * 8 + ((lane & 3) << 1) + (c & 1);
                    int rloc = wm * 32 + i * 16 + (c >> 1) * 8 + (lane >> 2);
                    float c1 = __fadd_rn(sxs[rloc], ses[n]);
                    float c2 = __fmul_rn(2.0f, acc[i][j][c]);
                    float D  = __fsub_rn(c1, c2);
                    unsigned long long key =
                        ((unsigned long long)__float_as_uint(D) << 32) | (unsigned)n;
                    int b = i * 2 + (c >> 1);
                    if (key < b1[b]) { b2[b] = b1[b]; b1[b] = key; }
                    else if (key < b2[b]) b2[b] = key;
                }
    }

    // merge top-2 across the 8 threads sharing each row (reuse stage smem)
    __syncthreads();
    unsigned long long* m1 = (unsigned long long*)sm;        // [128][8]
    unsigned long long* m2 = m1 + 1024;                      // [128][8]
    const int slot = wn * 4 + (lane & 3);
    #pragma unroll
    for (int b = 0; b < 4; b++) {
        int r = wm * 32 + (b >> 1) * 16 + (b & 1) * 8 + (lane >> 2);
        m1[r * 8 + slot] = b1[b];
        m2[r * 8 + slot] = b2[b];
    }
    __syncthreads();
    if (tid < 128) {
        unsigned long long K1 = ~0ull, K2 = ~0ull;
        #pragma unroll
        for (int t = 0; t < 8; t++) {
            unsigned long long v1 = m1[tid * 8 + t];
            unsigned long long v2 = m2[tid * 8 + t];
            if (v1 < K1) { K2 = K1; K1 = v1; }
            else if (v1 < K2) K2 = v1;
            if (v2 < K2) K2 = v2;
        }
        int row = row0 + tid;
        g_idx[row] = (int)(K1 & 0xffffffffu);
        float D1 = __uint_as_float((uint32_t)(K1 >> 32));
        float D2 = __uint_as_float((uint32_t)(K2 >> 32));
        if (D2 - D1 < GAPT) {
            int p = atomicAdd(&g_fcount, 1);
            g_flist[p] = row;
        }
    }
}

// ---------------------------------------------------------------------------
// Phase 2: exact fp32 re-argmin for uncertain rows (8 rows per CTA batch).
// ---------------------------------------------------------------------------
__global__ __launch_bounds__(256) void k_fallback(const float* __restrict__ x,
                                                  const float* __restrict__ emb) {
    __shared__ float xs[8][256];
    __shared__ float sxr[8];
    __shared__ unsigned long long bk[8];
    const int tid = threadIdx.x;
    const int count = g_fcount;

    for (int base = blockIdx.x * 8; base < count; base += gridDim.x * 8) {
        int nr = count - base; if (nr > 8) nr = 8;
        for (int r = 0; r < nr; r++) {
            int row = g_flist[base + r];
            int b = row >> 10, hw = row & 1023;
            xs[r][tid] = x[(size_t)b * (Cn * HWn) + (size_t)tid * HWn + hw];
        }
        if (tid < 8) bk[tid] = ~0ull;
        if (tid < nr) sxr[tid] = g_sx[g_flist[base + tid]];
        __syncthreads();

        #pragma unroll 1
        for (int kq = 0; kq < 4; kq++) {
            int k = kq * 256 + tid;
            float acc[8];
            #pragma unroll
            for (int r = 0; r < 8; r++) acc[r] = 0.f;
            const float* er = emb + (size_t)k * Cn;
            #pragma unroll 4
            for (int c = 0; c < Cn; c++) {
                float ev = er[c];
                #pragma unroll
                for (int r = 0; r < 8; r++) acc[r] = fmaf(xs[r][c], ev, acc[r]);
            }
            float sek = g_se[k];
            for (int r = 0; r < nr; r++) {
                float D = __fsub_rn(__fadd_rn(sxr[r], sek), __fmul_rn(2.0f, acc[r]));
                unsigned long long key =
                    ((unsigned long long)__float_as_uint(D) << 32) | (unsigned)k;
                atomicMin(&bk[r], key);
            }
        }
        __syncthreads();
        if (tid < nr) g_idx[g_flist[base + tid]] = (int)(bk[tid] & 0xffffffffu);
        __syncthreads();
    }
}

// ---------------------------------------------------------------------------
// Output: gather codes, write [B,C,H,W], accumulate MSE.
// ---------------------------------------------------------------------------
__global__ __launch_bounds__(256)
void k_output(const float* __restrict__ x, const float* __restrict__ emb,
              float* __restrict__ out, int write_tensor) {
    int blk = blockIdx.x;
    int b   = blk >> 4;
    int hw0 = (blk & 15) * 64;
    int tid = threadIdx.x;
    int h4  = tid & 15;
    int cgv = tid >> 4;
    int hw  = hw0 + h4 * 4;
    int n0  = b * HWn + hw;
    int i0 = g_idx[n0], i1 = g_idx[n0 + 1], i2 = g_idx[n0 + 2], i3 = g_idx[n0 + 3];
    const float* xb = x   + (size_t)b * (Cn * HWn) + hw;
    float*       ob = out + (size_t)b * (Cn * HWn) + hw;

    float accl = 0.f;
    #pragma unroll 4
    for (int cc = 0; cc < 16; cc++) {
        int c = cgv * 16 + cc;
        float q0 = emb[i0 * Cn + c];
        float q1 = emb[i1 * Cn + c];
        float q2 = emb[i2 * Cn + c];
        float q3 = emb[i3 * Cn + c];
        float4 xv = *(const float4*)&xb[c * HWn];
        float d0 = q0 - xv.x, d1 = q1 - xv.y, d2 = q2 - xv.z, d3 = q3 - xv.w;
        accl += d0 * d0 + d1 * d1 + d2 * d2 + d3 * d3;
        if (write_tensor) {
            float4 qv = make_float4(q0, q1, q2, q3);
            *(float4*)&ob[c * HWn] = qv;
        }
    }
    __shared__ float red[256];
    red[tid] = accl;
    __syncthreads();
    for (int s = 128; s; s >>= 1) {
        if (tid < s) red[tid] += red[tid + s];
        __syncthreads();
    }
    if (tid == 0) atomicAdd(&g_loss, (double)red[0]);
}

__global__ void k_finalize(float* out, int pos) {
    out[pos] = (float)(1.25 * g_loss / (double)NTENS);
}

// ---------------------------------------------------------------------------
extern "C" void kernel_launch(void* const* d_in, const int* in_sizes, int n_in,
                              void* d_out, int out_size) {
    const float* x   = (const float*)d_in[0];
    const float* emb = (const float*)d_in[1];
    float* out = (float*)d_out;

    cudaFuncSetAttribute(k_mma, cudaFuncAttributeMaxDynamicSharedMemorySize, SM_TOTAL);

    k_prepe<<<4, 256>>>(emb);
    k_split<<<1024, 256>>>(x);
    k_mma<<<NROWS / 128, 256, SM_TOTAL>>>();
    k_fallback<<<256, 256>>>(x, emb);

    int write_tensor = (out_size >= NTENS) ? 1 : 0;
    k_output<<<512, 256>>>(x, emb, out, write_tensor);

    if (out_size == NTENS + 1)      k_finalize<<<1, 1>>>(out, NTENS);
    else if (out_size == 1)         k_finalize<<<1, 1>>>(out, 0);
}

// round 5
// speedup vs baseline: 2.8016x; 1.7088x over previous
#include <cuda_runtime.h>
#include <cuda_fp16.h>
#include <cstdint>

#define Bn    32
#define Cn    256
#define HWn   1024
#define NROWS 32768
#define Kn    1024
#define NTENS 8388608

// ---------------- scratch (device globals; no allocation allowed) ----------
__device__ __align__(16) __half g_Ah[NROWS * Cn];     // 16MB fp16 x (transposed)
__device__ __align__(16) __half g_Eh[Kn * Cn];        // 0.5MB fp16 emb
__device__ __align__(16) float  g_xt[NROWS * Cn];     // 32MB fp32 x transposed
__device__ __align__(16) uint32_t g_q[NROWS * 512];   // 64MB u16 proxy (packed)
__device__ float  g_sx[NROWS];
__device__ float  g_se[Kn];
__device__ unsigned long long g_best[NROWS];
__device__ uint32_t g_cand[NROWS * 16];
__device__ int    g_ccount;
__device__ int    g_fullcnt;
__device__ int    g_fullrows[NROWS];
__device__ double g_loss;

// proxy quantization: q = floor((p + 0.8) * 40000), step 2.5e-5
#define QSCALE 40000.0f
#define QOFS   0.8f
#define QWIN   26            // 6.5e-4 window in q-steps

// ---------------- PTX helpers ----------------------------------------------
__device__ __forceinline__ uint32_t cvta_s(const void* p) {
    return (uint32_t)__cvta_generic_to_shared(p);
}
__device__ __forceinline__ void cp16(uint32_t dst, const void* src) {
    asm volatile("cp.async.cg.shared.global [%0], [%1], 16;"
                 :: "r"(dst), "l"(src) : "memory");
}
__device__ __forceinline__ void cp_commit() {
    asm volatile("cp.async.commit_group;" ::: "memory");
}
template <int N> __device__ __forceinline__ void cp_wait() {
    asm volatile("cp.async.wait_group %0;" :: "n"(N) : "memory");
}
__device__ __forceinline__ void ldsm4(uint32_t* r, uint32_t a) {
    asm volatile("ldmatrix.sync.aligned.m8n8.x4.shared.b16 {%0,%1,%2,%3},[%4];"
                 : "=r"(r[0]), "=r"(r[1]), "=r"(r[2]), "=r"(r[3]) : "r"(a));
}
__device__ __forceinline__ void mma16816(float* c, const uint32_t* a, const uint32_t* b) {
    asm volatile(
        "mma.sync.aligned.m16n8k16.row.col.f32.f16.f16.f32 "
        "{%0,%1,%2,%3},{%4,%5,%6,%7},{%8,%9},{%0,%1,%2,%3};"
        : "+f"(c[0]), "+f"(c[1]), "+f"(c[2]), "+f"(c[3])
        : "r"(a[0]), "r"(a[1]), "r"(a[2]), "r"(a[3]), "r"(b[0]), "r"(b[1]));
}

// ---------------------------------------------------------------------------
// Prep 1: emb -> fp16 + se (fp64->fp32); reset counters.
// ---------------------------------------------------------------------------
__global__ void k_prepe(const float* __restrict__ emb) {
    int k = blockIdx.x * 256 + threadIdx.x;
    if (k == 0) { g_loss = 0.0; g_ccount = 0; g_fullcnt = 0; }
    if (k >= Kn) return;
    const float* e = emb + (size_t)k * Cn;
    double s = 0.0;
    for (int g = 0; g < 32; g++) {
        float4 v0 = *(const float4*)(e + g * 8);
        float4 v1 = *(const float4*)(e + g * 8 + 4);
        float vv[8] = {v0.x, v0.y, v0.z, v0.w, v1.x, v1.y, v1.z, v1.w};
        __align__(16) __half hb[8];
        #pragma unroll
        for (int i = 0; i < 8; i++) {
            float v = vv[i];
            s += (double)v * (double)v;
            hb[i] = __float2half_rn(v);
        }
        *(uint4*)&g_Eh[(size_t)k * Cn + g * 8] = *(uint4*)hb;
    }
    g_se[k] = (float)s;
}

// ---------------------------------------------------------------------------
// Prep 2: x [B,C,H,W] -> fp16 transposed + fp32 transposed + sx per row.
// ---------------------------------------------------------------------------
__global__ __launch_bounds__(256) void k_split(const float* __restrict__ x) {
    __shared__ float  xs[256 * 33];
    __shared__ double ps[8][32];
    int blk = blockIdx.x;
    int b   = blk >> 5;
    int hw0 = (blk & 31) * 32;
    int tid = threadIdx.x;

    const float* xb = x + (size_t)b * (Cn * HWn) + hw0;
    #pragma unroll
    for (int t = 0; t < 8; t++) {
        int idx = tid + t * 256;
        int c = idx >> 3, g = idx & 7;
        float4 v = *(const float4*)(xb + (size_t)c * HWn + g * 4);
        xs[c * 33 + g * 4 + 0] = v.x;
        xs[c * 33 + g * 4 + 1] = v.y;
        xs[c * 33 + g * 4 + 2] = v.z;
        xs[c * 33 + g * 4 + 3] = v.w;
    }
    __syncthreads();

    int hw = tid & 31;
    int cs = tid >> 5;
    size_t n = (size_t)b * HWn + hw0 + hw;
    double s = 0.0;
    #pragma unroll 1
    for (int g = 0; g < 4; g++) {
        __align__(16) __half hb[8];
        __align__(16) float  fb[8];
        #pragma unroll
        for (int i = 0; i < 8; i++) {
            int c = cs * 32 + g * 8 + i;
            float v = xs[c * 33 + hw];
            s += (double)v * (double)v;
            hb[i] = __float2half_rn(v);
            fb[i] = v;
        }
        size_t o = n * Cn + cs * 32 + g * 8;
        *(uint4*)&g_Ah[o] = *(uint4*)hb;
        *(uint4*)&g_xt[o]     = *(uint4*)fb;
        *(uint4*)&g_xt[o + 4] = *(uint4*)(fb + 4);
    }
    ps[cs][hw] = s;
    __syncthreads();
    if (tid < 32) {
        double t = 0.0;
        #pragma unroll
        for (int j = 0; j < 8; j++) t += ps[j][tid];
        g_sx[(size_t)b * HWn + hw0 + tid] = (float)t;
    }
}

// ---------------------------------------------------------------------------
// Pruning GEMM: fp16, K=256. CTA: 128 rows x (8 blocks of 128 codes).
// A tile (64KB, 4 k-stages) resident; B double-buffered (2x16KB).
// Emits u16 proxy q = quant(se - 2*dot) to gmem.
// ---------------------------------------------------------------------------
#define SA_OFF   0
#define SB_OFF   65536
#define SES_OFF  (65536 + 32768)
#define SM_TOTAL (SES_OFF + 4096)   // 102400

__global__ __launch_bounds__(256, 2) void k_mma() {
    extern __shared__ char sm[];
    const uint32_t smem = cvta_s(sm);
    float* ses = (float*)(sm + SES_OFF);

    const int tid  = threadIdx.x;
    const int lane = tid & 31;
    const int wid  = tid >> 5;
    const int wm   = wid & 3;
    const int wn   = wid >> 2;
    const int row0 = blockIdx.x * 128;

    for (int i = tid; i < Kn; i += 256) ses[i] = g_se[i];

    // ---- preload A: 4 k-stages x 128 rows x 128B (one cp group) ----
    {
        const int g = tid & 7, rb = tid >> 3;
        #pragma unroll
        for (int t = 0; t < 16; t++) {
            int idx = tid + t * 256;
            int st = idx >> 10;
            int r  = (idx >> 3) & 127;
            int kc = idx & 7;
            // recompute from flat idx for uniqueness
            (void)g; (void)rb;
            uint32_t bo = (uint32_t)(r * 128 + kc * 16);
            cp16(smem + SA_OFF + st * 16384 + (bo ^ ((bo >> 3) & 0x70)),
                 g_Ah + (size_t)(row0 + r) * Cn + st * 64 + kc * 8);
        }
        cp_commit();
    }

    #define ISSUEB(T) do {                                                    \
        int _t = (T);                                                         \
        int _cb = _t >> 2, _s = _t & 3;                                       \
        const __half* _gb = g_Eh + (size_t)(_cb * 128) * Cn + _s * 64;        \
        uint32_t _b = smem + SB_OFF + (uint32_t)(_t & 1) * 16384;             \
        _Pragma("unroll")                                                     \
        for (int _tt = 0; _tt < 4; _tt++) {                                   \
            int _idx = tid + _tt * 256;                                       \
            int _r = _idx >> 3, _kc = _idx & 7;                               \
            uint32_t _bo = (uint32_t)(_r * 128 + _kc * 16);                   \
            cp16(_b + (_bo ^ ((_bo >> 3) & 0x70)),                            \
                 _gb + (size_t)_r * Cn + _kc * 8);                            \
        }                                                                     \
        cp_commit();                                                          \
    } while (0)

    ISSUEB(0);

    const int arow0 = wm * 32 + (lane & 15);
    const int akofs = (lane >> 4);
    const int bnofs = ((lane >> 4) << 3) + (lane & 7);
    const int bkofs = ((lane >> 3) & 1);

    float acc[2][8][4];
    #pragma unroll
    for (int i = 0; i < 2; i++)
        #pragma unroll
        for (int j = 0; j < 8; j++)
            #pragma unroll
            for (int c = 0; c < 4; c++) acc[i][j][c] = 0.f;

    for (int t = 0; t < 32; t++) {
        __syncthreads();                 // all warps done with prior buffers
        if (t + 1 < 32) { ISSUEB(t + 1); cp_wait<1>(); }
        else           cp_wait<0>();
        __syncthreads();

        const int s = t & 3;
        const uint32_t sA = smem + SA_OFF + (uint32_t)s * 16384;
        const uint32_t sB = smem + SB_OFF + (uint32_t)(t & 1) * 16384;

        #pragma unroll
        for (int ks = 0; ks < 4; ks++) {
            uint32_t af[2][4], bf[4][4];
            #pragma unroll
            for (int i = 0; i < 2; i++) {
                int r = arow0 + i * 16;
                int kc = ks * 2 + akofs;
                ldsm4(af[i], sA + r * 128 + ((kc ^ (r & 7)) << 4));
            }
            #pragma unroll
            for (int p = 0; p < 4; p++) {
                int n = wn * 64 + p * 16 + bnofs;
                int kc = ks * 2 + bkofs;
                ldsm4(bf[p], sB + n * 128 + ((kc ^ (n & 7)) << 4));
            }
            #pragma unroll
            for (int i = 0; i < 2; i++)
                #pragma unroll
                for (int j = 0; j < 8; j++)
                    mma16816(acc[i][j], af[i], &bf[j >> 1][(j & 1) * 2]);
        }

        if (s == 3) {   // end of code-block cb: emit proxies, reset acc
            const int cb = t >> 2;
            #pragma unroll
            for (int i = 0; i < 2; i++) {
                #pragma unroll
                for (int j = 0; j < 8; j++) {
                    int ncode = cb * 128 + wn * 64 + j * 8 + (lane & 3) * 2;
                    uint32_t qv[4];
                    #pragma unroll
                    for (int c = 0; c < 4; c++) {
                        float p = __fmaf_rn(-2.0f, acc[i][j][c], ses[ncode + (c & 1)]);
                        float qf = (p + QOFS) * QSCALE;
                        qf = fminf(fmaxf(qf, 0.f), 65535.f);
                        qv[c] = (uint32_t)qf;
                        acc[i][j][c] = 0.f;
                    }
                    int ra = row0 + wm * 32 + i * 16 + (lane >> 2);
                    uint32_t col = (uint32_t)(cb * 64 + wn * 32 + j * 4 + (lane & 3));
                    g_q[(size_t)ra * 512 + col]         = qv[0] | (qv[1] << 16);
                    g_q[(size_t)(ra + 8) * 512 + col]   = qv[2] | (qv[3] << 16);
                }
            }
        }
    }
    #undef ISSUEB
}

// ---------------------------------------------------------------------------
// Select: per row (warp): min proxy, push candidates within QWIN.
// ---------------------------------------------------------------------------
__global__ __launch_bounds__(256) void k_select() {
    const int tid  = threadIdx.x;
    const int lane = tid & 31;
    const int row  = blockIdx.x * 8 + (tid >> 5);

    const uint4* qr = (const uint4*)(g_q + (size_t)row * 512);
    uint4 v[4];
    #pragma unroll
    for (int c4 = 0; c4 < 4; c4++) v[c4] = qr[lane + 32 * c4];

    uint32_t mn = 0xffffu;
    #pragma unroll
    for (int c4 = 0; c4 < 4; c4++) {
        uint32_t w[4] = {v[c4].x, v[c4].y, v[c4].z, v[c4].w};
        #pragma unroll
        for (int k = 0; k < 4; k++) {
            uint32_t lo = w[k] & 0xffffu, hi = w[k] >> 16;
            mn = min(mn, min(lo, hi));
        }
    }
    #pragma unroll
    for (int o = 16; o; o >>= 1)
        mn = min(mn, __shfl_xor_sync(0xffffffffu, mn, o));

    const uint32_t thr = mn + QWIN;

    // count hits per lane
    int cnt = 0;
    #pragma unroll
    for (int c4 = 0; c4 < 4; c4++) {
        uint32_t w[4] = {v[c4].x, v[c4].y, v[c4].z, v[c4].w};
        #pragma unroll
        for (int k = 0; k < 4; k++) {
            if ((w[k] & 0xffffu) <= thr) cnt++;
            if ((w[k] >> 16)    <= thr) cnt++;
        }
    }
    // exclusive prefix over lanes
    int pfx = cnt;
    #pragma unroll
    for (int o = 1; o < 32; o <<= 1) {
        int u = __shfl_up_sync(0xffffffffu, pfx, o);
        if (lane >= o) pfx += u;
    }
    int total = __shfl_sync(0xffffffffu, pfx, 31);
    pfx -= cnt;

    if (total <= 16) {
        int base = 0;
        if (lane == 0 && total > 0) base = atomicAdd(&g_ccount, total);
        base = __shfl_sync(0xffffffffu, base, 0);
        int o = 0;
        #pragma unroll
        for (int c4 = 0; c4 < 4; c4++) {
            uint32_t w[4] = {v[c4].x, v[c4].y, v[c4].z, v[c4].w};
            #pragma unroll
            for (int k = 0; k < 4; k++) {
                int m = 4 * (lane + 32 * c4) + k;   // u32 index -> codes 2m,2m+1
                if ((w[k] & 0xffffu) <= thr)
                    g_cand[base + pfx + (o++)] = ((uint32_t)row << 10) | (2 * m);
                if ((w[k] >> 16) <= thr)
                    g_cand[base + pfx + (o++)] = ((uint32_t)row << 10) | (2 * m + 1);
            }
        }
    } else {
        if (lane == 0) {
            int fi = atomicAdd(&g_fullcnt, 1);
            g_fullrows[fi] = row;
        }
    }
    if (lane == 0) g_best[row] = ~0ull;
}

// ---------------------------------------------------------------------------
// Exact resolution: sequential fp32 dot per candidate (proven arithmetic).
// ---------------------------------------------------------------------------
__global__ __launch_bounds__(256) void k_exact(const float* __restrict__ emb) {
    const int total = g_ccount;
    for (int i = blockIdx.x * 256 + threadIdx.x; i < total; i += gridDim.x * 256) {
        uint32_t rc = g_cand[i];
        int row = rc >> 10, code = rc & 1023;
        const float* xr = g_xt + (size_t)row * Cn;
        const float* er = emb  + (size_t)code * Cn;
        float acc = 0.f;
        #pragma unroll 8
        for (int c = 0; c < Cn; c++) acc = fmaf(xr[c], er[c], acc);
        float D = __fsub_rn(__fadd_rn(g_sx[row], g_se[code]),
                            __fmul_rn(2.0f, acc));
        unsigned long long key =
            ((unsigned long long)__float_as_uint(D) << 32) | (unsigned)code;
        atomicMin(&g_best[row], key);
    }
}

// ---------------------------------------------------------------------------
// Safety net: full exact argmin for overflow rows (expected zero).
// ---------------------------------------------------------------------------
__global__ __launch_bounds__(256) void k_full(const float* __restrict__ emb) {
    __shared__ float xs[256];
    __shared__ unsigned long long bk;
    const int tid = threadIdx.x;
    const int nfull = g_fullcnt;
    for (int fi = blockIdx.x; fi < nfull; fi += gridDim.x) {
        int row = g_fullrows[fi];
        xs[tid] = g_xt[(size_t)row * Cn + tid];
        if (tid == 0) bk = ~0ull;
        __syncthreads();
        float sx = g_sx[row];
        #pragma unroll 1
        for (int kq = 0; kq < 4; kq++) {
            int k = kq * 256 + tid;
            const float* er = emb + (size_t)k * Cn;
            float acc = 0.f;
            #pragma unroll 8
            for (int c = 0; c < Cn; c++) acc = fmaf(xs[c], er[c], acc);
            float D = __fsub_rn(__fadd_rn(sx, g_se[k]), __fmul_rn(2.0f, acc));
            unsigned long long key =
                ((unsigned long long)__float_as_uint(D) << 32) | (unsigned)k;
            atomicMin(&bk, key);
        }
        __syncthreads();
        if (tid == 0) atomicMin(&g_best[row], bk);
        __syncthreads();
    }
}

// ---------------------------------------------------------------------------
// Output: gather codes, write [B,C,H,W], accumulate MSE.
// ---------------------------------------------------------------------------
__global__ __launch_bounds__(256)
void k_output(const float* __restrict__ x, const float* __restrict__ emb,
              float* __restrict__ out, int write_tensor) {
    int blk = blockIdx.x;
    int b   = blk >> 4;
    int hw0 = (blk & 15) * 64;
    int tid = threadIdx.x;
    int h4  = tid & 15;
    int cgv = tid >> 4;
    int hw  = hw0 + h4 * 4;
    int n0  = b * HWn + hw;
    int i0 = (int)(g_best[n0]     & 0xffffffffu);
    int i1 = (int)(g_best[n0 + 1] & 0xffffffffu);
    int i2 = (int)(g_best[n0 + 2] & 0xffffffffu);
    int i3 = (int)(g_best[n0 + 3] & 0xffffffffu);
    const float* xb = x   + (size_t)b * (Cn * HWn) + hw;
    float*       ob = out + (size_t)b * (Cn * HWn) + hw;

    float accl = 0.f;
    #pragma unroll 4
    for (int cc = 0; cc < 16; cc++) {
        int c = cgv * 16 + cc;
        float q0 = emb[i0 * Cn + c];
        float q1 = emb[i1 * Cn + c];
        float q2 = emb[i2 * Cn + c];
        float q3 = emb[i3 * Cn + c];
        float4 xv = *(const float4*)&xb[c * HWn];
        float d0 = q0 - xv.x, d1 = q1 - xv.y, d2 = q2 - xv.z, d3 = q3 - xv.w;
        accl += d0 * d0 + d1 * d1 + d2 * d2 + d3 * d3;
        if (write_tensor) {
            float4 qv = make_float4(q0, q1, q2, q3);
            *(float4*)&ob[c * HWn] = qv;
        }
    }
    __shared__ float red[256];
    red[tid] = accl;
    __syncthreads();
    for (int s = 128; s; s >>= 1) {
        if (tid < s) red[tid] += red[tid + s];
        __syncthreads();
    }
    if (tid == 0) atomicAdd(&g_loss, (double)red[0]);
}

__global__ void k_finalize(float* out, int pos) {
    out[pos] = (float)(1.25 * g_loss / (double)NTENS);
}

// ---------------------------------------------------------------------------
extern "C" void kernel_launch(void* const* d_in, const int* in_sizes, int n_in,
                              void* d_out, int out_size) {
    const float* x   = (const float*)d_in[0];
    const float* emb = (const float*)d_in[1];
    float* out = (float*)d_out;

    cudaFuncSetAttribute(k_mma, cudaFuncAttributeMaxDynamicSharedMemorySize, SM_TOTAL);

    k_prepe<<<4, 256>>>(emb);
    k_split<<<1024, 256>>>(x);
    k_mma<<<NROWS / 128, 256, SM_TOTAL>>>();
    k_select<<<NROWS / 8, 256>>>();
    k_exact<<<256, 256>>>(emb);
    k_full<<<64, 256>>>(emb);

    int write_tensor = (out_size >= NTENS) ? 1 : 0;
    k_output<<<512, 256>>>(x, emb, out, write_tensor);

    if (out_size == NTENS + 1)      k_finalize<<<1, 1>>>(out, NTENS);
    else if (out_size == 1)         k_finalize<<<1, 1>>>(out, 0);
}